// round 3
// baseline (speedup 1.0000x reference)
#include <cuda_runtime.h>
#include <cuda_bf16.h>

// ---------------------------------------------------------------------------
// PSA3D: permuted 3D window attention
//   B=512 windows, N=512 tokens/window, C=192, 6 heads x 32, P=64 kv tokens
// Pipeline:
//   K0: bias precompute  g_bias[h][pq][p] = bias_table[rpi[n(pq),p], h]   (rpi has only 64 distinct rows)
//   K1: fused qkv GEMM   x(262144,192) @ [wq|wkv](192,240) -> g_q (scaled), g_k/g_v (scattered to [b,h,p,d])
//   K2: attention        per (b,h): S=QK^T (tf32 mma) + bias, softmax, O=PV (tf32 mma) -> g_ao
//   K3: out proj GEMM    g_ao @ wproj + bproj -> d_out
// ---------------------------------------------------------------------------

#define BWIN   512
#define NTOK   512
#define CDIM   192
#define NH     6
#define HD     32
#define PKV    64
#define MROWS  (BWIN * NTOK)          // 262144
#define SCALE_F 0.17677669529663687f  // 32^-0.5

// scratch (static device arrays; no dynamic allocation allowed)
__device__ __align__(16) float g_q [MROWS * CDIM];          // 201 MB, pre-scaled q, (m, c) row-major
__device__ __align__(16) float g_k [BWIN * NH * PKV * HD];  // 25 MB, [b][h][p][d]
__device__ __align__(16) float g_v [BWIN * NH * PKV * HD];  // 25 MB
__device__ __align__(16) float g_ao[MROWS * CDIM];          // 201 MB, attention output (m, c)
__device__ __align__(16) float g_bias[NH * 64 * 64];        // 96 KB

// ---------------------------------------------------------------------------
// helpers
// ---------------------------------------------------------------------------
__device__ __forceinline__ unsigned f2tf(float f) {
    unsigned u;
    asm("cvt.rna.tf32.f32 %0, %1;" : "=r"(u) : "f"(f));
    return u;
}

__device__ __forceinline__ void mma8(float* c, unsigned a0, unsigned a1, unsigned a2, unsigned a3,
                                     unsigned b0, unsigned b1) {
    asm volatile(
        "mma.sync.aligned.m16n8k8.row.col.f32.tf32.tf32.f32 "
        "{%0,%1,%2,%3}, {%4,%5,%6,%7}, {%8,%9}, {%0,%1,%2,%3};\n"
        : "+f"(c[0]), "+f"(c[1]), "+f"(c[2]), "+f"(c[3])
        : "r"(a0), "r"(a1), "r"(a2), "r"(a3), "r"(b0), "r"(b1));
}

// pq (permuted-window coarse position) of token n
// n = pd*128 + sd*64 + ph*16 + sh*8 + pw*2 + sw ; pq = pd*16 + ph*4 + pw
__device__ __forceinline__ int pq_of(int n) {
    return ((n >> 7) << 4) | (((n >> 4) & 3) << 2) | ((n >> 1) & 3);
}

// ---------------------------------------------------------------------------
// K0: bias precompute.  g_bias[h][pq][p] = bias_table[rpi[n(pq)*64+p], h]
// ---------------------------------------------------------------------------
__global__ void bias_kernel(const float* __restrict__ bias_table, const int* __restrict__ rpi) {
    int i = blockIdx.x * blockDim.x + threadIdx.x;   // 6*64*64 = 24576
    if (i >= NH * 64 * 64) return;
    int h  = i >> 12;
    int pq = (i >> 6) & 63;
    int p  = i & 63;
    int pd = pq >> 4, ph = (pq >> 2) & 3, pw = pq & 3;
    int n  = pd * 128 + ph * 16 + pw * 2;            // representative token (sub-pos 0,0,0)
    int t  = rpi[n * 64 + p];
    g_bias[i] = bias_table[t * NH + h];
}

// ---------------------------------------------------------------------------
// GEMM: BM=128, BK=32, 384 threads (12 warps: 4 M x 3 N), tf32 mma m16n8k8
//   EPI=0: qkv (BN=240): B0=wq(192), B1=wkv(48); write g_q (scaled) + scatter g_k/g_v
//   EPI=1: proj (BN=192): B0=wproj; out = A @ B0 + bias0 -> out
// ---------------------------------------------------------------------------
__device__ __forceinline__ void epi0_store(int r, int c, float val,
                                           const float* __restrict__ bq,
                                           const float* __restrict__ bkv) {
    if (c < 192) {
        g_q[r * CDIM + c] = (val + bq[c]) * SCALE_F;
    } else {
        int ch = c - 192;
        float v = val + bkv[ch];
        int b = r >> 9, n = r & 511;
        int d_ = n >> 6, h_ = (n >> 3) & 7, w_ = n & 7;   // full 8x8x8 coords
        int p  = ((d_ >> 1) << 4) | ((h_ >> 1) << 2) | (w_ >> 1);
        int s  = ((d_ & 1) << 2) | ((h_ & 1) << 1) | (w_ & 1);
        int off = s * 48 + ch;                        // 0..383; <192 -> k, else v
        if (off < 192) {
            g_k[((b * NH + (off >> 5)) * PKV + p) * HD + (off & 31)] = v;
        } else {
            int o2 = off - 192;
            g_v[((b * NH + (o2 >> 5)) * PKV + p) * HD + (o2 & 31)] = v;
        }
    }
}

template<int BN, int EPI>
__global__ __launch_bounds__(384)
void gemm_kernel(const float* __restrict__ A,
                 const float* __restrict__ B0,
                 const float* __restrict__ B1,
                 const float* __restrict__ bias0,
                 const float* __restrict__ bias1,
                 float* __restrict__ out) {
    constexpr int NTW = BN / 24;            // n8-tiles per warp (10 or 8)
    constexpr int WN  = BN / 3;             // warp n extent (80 or 64)
    constexpr int BNP = (BN == 240) ? 260 : 196;   // pad: BNP % 32 == 4 keeps frag loads conflict-light

    __shared__ unsigned As[128][36];        // tf32 bits
    __shared__ unsigned Bs[32][BNP];

    const float* Ap = (EPI == 0) ? A : (const float*)g_ao;

    int tid  = threadIdx.x;
    int wid  = tid >> 5;
    int lane = tid & 31;
    int g    = lane >> 2;
    int t    = lane & 3;
    int wm   = wid / 3;                     // 0..3 -> rows wm*32
    int wn   = wid % 3;                     // cols wn*WN
    int m0   = blockIdx.x * 128;

    float acc[2][NTW][4];
    #pragma unroll
    for (int mt = 0; mt < 2; mt++)
        #pragma unroll
        for (int nt = 0; nt < NTW; nt++)
            #pragma unroll
            for (int j = 0; j < 4; j++) acc[mt][nt][j] = 0.f;

    for (int ko = 0; ko < 6; ko++) {        // K = 192 = 6 * 32
        // A tile 128x32 (1024 float4 loads)
        for (int i = tid; i < 1024; i += 384) {
            int r = i >> 3, c = (i & 7) << 2;
            const float4 v4 = *(const float4*)(Ap + (size_t)(m0 + r) * CDIM + ko * 32 + c);
            As[r][c + 0] = f2tf(v4.x);
            As[r][c + 1] = f2tf(v4.y);
            As[r][c + 2] = f2tf(v4.z);
            As[r][c + 3] = f2tf(v4.w);
        }
        // B tile 32xBN
        for (int i = tid; i < 32 * BN; i += 384) {
            int kr = i / BN, c = i % BN;
            float v;
            if (EPI == 0) {
                v = (c < 192) ? B0[(ko * 32 + kr) * 192 + c]
                              : B1[(ko * 32 + kr) * 48 + (c - 192)];
            } else {
                v = B0[(ko * 32 + kr) * 192 + c];
            }
            Bs[kr][c] = f2tf(v);
        }
        __syncthreads();

        #pragma unroll
        for (int kk = 0; kk < 4; kk++) {
            unsigned a[2][4];
            #pragma unroll
            for (int mt = 0; mt < 2; mt++) {
                int row = wm * 32 + mt * 16;
                a[mt][0] = As[row + g    ][kk * 8 + t    ];
                a[mt][1] = As[row + g + 8][kk * 8 + t    ];
                a[mt][2] = As[row + g    ][kk * 8 + t + 4];
                a[mt][3] = As[row + g + 8][kk * 8 + t + 4];
            }
            unsigned b[NTW][2];
            #pragma unroll
            for (int nt = 0; nt < NTW; nt++) {
                int col = wn * WN + nt * 8 + g;
                b[nt][0] = Bs[kk * 8 + t    ][col];
                b[nt][1] = Bs[kk * 8 + t + 4][col];
            }
            #pragma unroll
            for (int mt = 0; mt < 2; mt++)
                #pragma unroll
                for (int nt = 0; nt < NTW; nt++)
                    mma8(acc[mt][nt], a[mt][0], a[mt][1], a[mt][2], a[mt][3], b[nt][0], b[nt][1]);
        }
        __syncthreads();
    }

    // epilogue
    #pragma unroll
    for (int mt = 0; mt < 2; mt++) {
        int r0 = m0 + wm * 32 + mt * 16 + g;
        int r1 = r0 + 8;
        #pragma unroll
        for (int nt = 0; nt < NTW; nt++) {
            int c0 = wn * WN + nt * 8 + 2 * t;
            int c1 = c0 + 1;
            if (EPI == 0) {
                epi0_store(r0, c0, acc[mt][nt][0], bias0, bias1);
                epi0_store(r0, c1, acc[mt][nt][1], bias0, bias1);
                epi0_store(r1, c0, acc[mt][nt][2], bias0, bias1);
                epi0_store(r1, c1, acc[mt][nt][3], bias0, bias1);
            } else {
                out[r0 * CDIM + c0] = acc[mt][nt][0] + bias0[c0];
                out[r0 * CDIM + c1] = acc[mt][nt][1] + bias0[c1];
                out[r1 * CDIM + c0] = acc[mt][nt][2] + bias0[c0];
                out[r1 * CDIM + c1] = acc[mt][nt][3] + bias0[c1];
            }
        }
    }
}

// ---------------------------------------------------------------------------
// K2: attention. grid (512, 6), 256 threads (8 warps).
// Each warp handles a 16-row query tile; 4 iterations cover 512 rows.
// ---------------------------------------------------------------------------
__global__ __launch_bounds__(256)
void attn_kernel() {
    __shared__ unsigned ks[64][36];   // k tf32, [p][d], pad 36 -> conflict-free frag loads
    __shared__ unsigned vs[64][33];   // v tf32, [p][d]
    __shared__ float    bs[64][65];   // bias [pq][p]

    int b = blockIdx.x;
    int h = blockIdx.y;
    int tid = threadIdx.x;

    const float* kp = g_k + (size_t)(b * NH + h) * (PKV * HD);
    const float* vp = g_v + (size_t)(b * NH + h) * (PKV * HD);
    for (int i = tid; i < PKV * HD; i += 256) {
        ks[i >> 5][i & 31] = f2tf(kp[i]);
        vs[i >> 5][i & 31] = f2tf(vp[i]);
    }
    const float* bp = g_bias + h * 4096;
    for (int i = tid; i < 4096; i += 256) bs[i >> 6][i & 63] = bp[i];
    __syncthreads();

    int wid  = tid >> 5;
    int lane = tid & 31;
    int g    = lane >> 2;
    int t    = lane & 3;
    int qsrc = (lane & ~3) + (t >> 1);        // shfl source for P C->A transpose (cols t, t+4 parity-selected)

    const float* qb = g_q  + (size_t)b * NTOK * CDIM + h * HD;
    float*       ob = g_ao + (size_t)b * NTOK * CDIM + h * HD;

    for (int it = 0; it < 4; it++) {
        int rowbase = it * 128 + wid * 16;

        // ---- S = Q K^T : (16 x 64), 8 n-tiles ----
        float s[8][4];
        #pragma unroll
        for (int nt = 0; nt < 8; nt++)
            #pragma unroll
            for (int j = 0; j < 4; j++) s[nt][j] = 0.f;

        #pragma unroll
        for (int kk = 0; kk < 4; kk++) {
            unsigned a0 = f2tf(qb[(rowbase + g    ) * CDIM + kk * 8 + t    ]);
            unsigned a1 = f2tf(qb[(rowbase + g + 8) * CDIM + kk * 8 + t    ]);
            unsigned a2 = f2tf(qb[(rowbase + g    ) * CDIM + kk * 8 + t + 4]);
            unsigned a3 = f2tf(qb[(rowbase + g + 8) * CDIM + kk * 8 + t + 4]);
            #pragma unroll
            for (int nt = 0; nt < 8; nt++) {
                unsigned b0 = ks[nt * 8 + g][kk * 8 + t    ];
                unsigned b1 = ks[nt * 8 + g][kk * 8 + t + 4];
                mma8(s[nt], a0, a1, a2, a3, b0, b1);
            }
        }

        // ---- bias + softmax over 64 cols (rows r0=rowbase+g, r1=r0+8) ----
        int r0 = rowbase + g, r1 = r0 + 8;
        int pq0 = pq_of(r0), pq1 = pq_of(r1);
        float m0 = -1e30f, m1 = -1e30f;
        #pragma unroll
        for (int nt = 0; nt < 8; nt++) {
            int c0 = nt * 8 + 2 * t;
            s[nt][0] += bs[pq0][c0];
            s[nt][1] += bs[pq0][c0 + 1];
            s[nt][2] += bs[pq1][c0];
            s[nt][3] += bs[pq1][c0 + 1];
            m0 = fmaxf(m0, fmaxf(s[nt][0], s[nt][1]));
            m1 = fmaxf(m1, fmaxf(s[nt][2], s[nt][3]));
        }
        m0 = fmaxf(m0, __shfl_xor_sync(0xffffffffu, m0, 1));
        m0 = fmaxf(m0, __shfl_xor_sync(0xffffffffu, m0, 2));
        m1 = fmaxf(m1, __shfl_xor_sync(0xffffffffu, m1, 1));
        m1 = fmaxf(m1, __shfl_xor_sync(0xffffffffu, m1, 2));
        float sum0 = 0.f, sum1 = 0.f;
        #pragma unroll
        for (int nt = 0; nt < 8; nt++) {
            s[nt][0] = __expf(s[nt][0] - m0); sum0 += s[nt][0];
            s[nt][1] = __expf(s[nt][1] - m0); sum0 += s[nt][1];
            s[nt][2] = __expf(s[nt][2] - m1); sum1 += s[nt][2];
            s[nt][3] = __expf(s[nt][3] - m1); sum1 += s[nt][3];
        }
        sum0 += __shfl_xor_sync(0xffffffffu, sum0, 1);
        sum0 += __shfl_xor_sync(0xffffffffu, sum0, 2);
        sum1 += __shfl_xor_sync(0xffffffffu, sum1, 1);
        sum1 += __shfl_xor_sync(0xffffffffu, sum1, 2);
        float inv0 = 1.f / sum0, inv1 = 1.f / sum1;

        unsigned pf[8][4];
        #pragma unroll
        for (int nt = 0; nt < 8; nt++) {
            pf[nt][0] = f2tf(s[nt][0] * inv0);
            pf[nt][1] = f2tf(s[nt][1] * inv0);
            pf[nt][2] = f2tf(s[nt][2] * inv1);
            pf[nt][3] = f2tf(s[nt][3] * inv1);
        }

        // ---- O = P V : (16 x 32), K=64 over 8 k-steps; A frags via quad shfl transpose ----
        float o[4][4];
        #pragma unroll
        for (int on = 0; on < 4; on++)
            #pragma unroll
            for (int j = 0; j < 4; j++) o[on][j] = 0.f;

        #pragma unroll
        for (int kt = 0; kt < 8; kt++) {
            // C-layout: thread t holds cols {2t, 2t+1}; A-layout needs cols {t, t+4}
            unsigned u00 = __shfl_sync(0xffffffffu, pf[kt][0], qsrc);
            unsigned u01 = __shfl_sync(0xffffffffu, pf[kt][1], qsrc);
            unsigned u10 = __shfl_sync(0xffffffffu, pf[kt][2], qsrc);
            unsigned u11 = __shfl_sync(0xffffffffu, pf[kt][3], qsrc);
            unsigned w00 = __shfl_sync(0xffffffffu, pf[kt][0], qsrc + 2);
            unsigned w01 = __shfl_sync(0xffffffffu, pf[kt][1], qsrc + 2);
            unsigned w10 = __shfl_sync(0xffffffffu, pf[kt][2], qsrc + 2);
            unsigned w11 = __shfl_sync(0xffffffffu, pf[kt][3], qsrc + 2);
            unsigned a0 = (t & 1) ? u01 : u00;   // P[r0][kt*8 + t]
            unsigned a1 = (t & 1) ? u11 : u10;   // P[r1][kt*8 + t]
            unsigned a2 = (t & 1) ? w01 : w00;   // P[r0][kt*8 + t + 4]
            unsigned a3 = (t & 1) ? w11 : w10;   // P[r1][kt*8 + t + 4]
            #pragma unroll
            for (int on = 0; on < 4; on++) {
                unsigned b0 = vs[kt * 8 + t    ][on * 8 + g];
                unsigned b1 = vs[kt * 8 + t + 4][on * 8 + g];
                mma8(o[on], a0, a1, a2, a3, b0, b1);
            }
        }

        // ---- write O tile ----
        #pragma unroll
        for (int on = 0; on < 4; on++) {
            int c0 = on * 8 + 2 * t;
            ob[r0 * CDIM + c0    ] = o[on][0];
            ob[r0 * CDIM + c0 + 1] = o[on][1];
            ob[r1 * CDIM + c0    ] = o[on][2];
            ob[r1 * CDIM + c0 + 1] = o[on][3];
        }
    }
}

// ---------------------------------------------------------------------------
// launch
// ---------------------------------------------------------------------------
extern "C" void kernel_launch(void* const* d_in, const int* in_sizes, int n_in,
                              void* d_out, int out_size) {
    const float* x          = (const float*)d_in[0];
    const float* wq         = (const float*)d_in[1];
    const float* bq         = (const float*)d_in[2];
    const float* wkv        = (const float*)d_in[3];
    const float* bkv        = (const float*)d_in[4];
    const float* bias_table = (const float*)d_in[5];
    const float* wproj      = (const float*)d_in[6];
    const float* bproj      = (const float*)d_in[7];
    const int*   rpi        = (const int*)d_in[8];
    float* out = (float*)d_out;

    bias_kernel<<<(NH * 64 * 64 + 255) / 256, 256>>>(bias_table, rpi);
    gemm_kernel<240, 0><<<MROWS / 128, 384>>>(x, wq, wkv, bq, bkv, nullptr);
    attn_kernel<<<dim3(BWIN, NH), 256>>>();
    gemm_kernel<192, 1><<<MROWS / 128, 384>>>(nullptr, wproj, nullptr, bproj, nullptr, out);
}

// round 6
// speedup vs baseline: 1.6077x; 1.6077x over previous
#include <cuda_runtime.h>
#include <cuda_bf16.h>

// ---------------------------------------------------------------------------
// PSA3D: permuted 3D window attention
//   B=512 windows, N=512 tokens/window, C=192, 6 heads x 32, P=64 kv tokens
// Pipeline:
//   K0: bias precompute  g_bias[h][pq][p] = bias_table[rpi[n(pq),p], h]
//   K1: fused qkv GEMM   x @ [wq|wkv] -> g_q (scaled), g_k/g_v scattered   (double-buffered)
//   K2: attention        per (b,h): S=QK^T + bias, softmax, O=PV (tf32 mma)
//   K3: out proj GEMM    g_ao @ wproj + bproj -> d_out                      (double-buffered)
// ---------------------------------------------------------------------------

#define BWIN   512
#define NTOK   512
#define CDIM   192
#define NH     6
#define HD     32
#define PKV    64
#define MROWS  (BWIN * NTOK)          // 262144
#define SCALE_F 0.17677669529663687f  // 32^-0.5

__device__ __align__(16) float g_q [MROWS * CDIM];
__device__ __align__(16) float g_k [BWIN * NH * PKV * HD];
__device__ __align__(16) float g_v [BWIN * NH * PKV * HD];
__device__ __align__(16) float g_ao[MROWS * CDIM];
__device__ __align__(16) float g_bias[NH * 64 * 64];

// ---------------------------------------------------------------------------
__device__ __forceinline__ unsigned f2tf(float f) {
    unsigned u;
    asm("cvt.rna.tf32.f32 %0, %1;" : "=r"(u) : "f"(f));
    return u;
}

__device__ __forceinline__ void mma8(float* c, unsigned a0, unsigned a1, unsigned a2, unsigned a3,
                                     unsigned b0, unsigned b1) {
    asm volatile(
        "mma.sync.aligned.m16n8k8.row.col.f32.tf32.tf32.f32 "
        "{%0,%1,%2,%3}, {%4,%5,%6,%7}, {%8,%9}, {%0,%1,%2,%3};\n"
        : "+f"(c[0]), "+f"(c[1]), "+f"(c[2]), "+f"(c[3])
        : "r"(a0), "r"(a1), "r"(a2), "r"(a3), "r"(b0), "r"(b1));
}

__device__ __forceinline__ int pq_of(int n) {
    return ((n >> 7) << 4) | (((n >> 4) & 3) << 2) | ((n >> 1) & 3);
}

// ---------------------------------------------------------------------------
// K0: bias precompute
// ---------------------------------------------------------------------------
__global__ void bias_kernel(const float* __restrict__ bias_table, const int* __restrict__ rpi) {
    int i = blockIdx.x * blockDim.x + threadIdx.x;   // 24576
    if (i >= NH * 64 * 64) return;
    int h  = i >> 12;
    int pq = (i >> 6) & 63;
    int p  = i & 63;
    int pd = pq >> 4, ph = (pq >> 2) & 3, pw = pq & 3;
    int n  = pd * 128 + ph * 16 + pw * 2;
    int t  = rpi[n * 64 + p];
    g_bias[i] = bias_table[t * NH + h];
}

// ---------------------------------------------------------------------------
// GEMM: BM=128, BK=32, 384 threads (12 warps: 4M x 3N), tf32 mma m16n8k8.
// Register-staged double buffering: prefetch tile ko+1 into regs during
// compute of tile ko; STS after compute; ONE syncthreads per k-iter.
// ---------------------------------------------------------------------------
__device__ __forceinline__ void epi0_store(int r, int c, float val,
                                           const float* __restrict__ bq,
                                           const float* __restrict__ bkv) {
    if (c < 192) {
        g_q[r * CDIM + c] = (val + bq[c]) * SCALE_F;
    } else {
        int ch = c - 192;
        float v = val + bkv[ch];
        int b = r >> 9, n = r & 511;
        int d_ = n >> 6, h_ = (n >> 3) & 7, w_ = n & 7;
        int p  = ((d_ >> 1) << 4) | ((h_ >> 1) << 2) | (w_ >> 1);
        int s  = ((d_ & 1) << 2) | ((h_ & 1) << 1) | (w_ & 1);
        int off = s * 48 + ch;
        if (off < 192) {
            g_k[((b * NH + (off >> 5)) * PKV + p) * HD + (off & 31)] = v;
        } else {
            int o2 = off - 192;
            g_v[((b * NH + (o2 >> 5)) * PKV + p) * HD + (o2 & 31)] = v;
        }
    }
}

template<int BN, int EPI>
__global__ __launch_bounds__(384)
void gemm_kernel(const float* __restrict__ A,
                 const float* __restrict__ B0,
                 const float* __restrict__ B1,
                 const float* __restrict__ bias0,
                 const float* __restrict__ bias1,
                 float* __restrict__ out) {
    constexpr int NTW = BN / 24;                   // 10 or 8
    constexpr int WN  = BN / 3;                    // 80 or 64
    constexpr int BNP = (BN == 240) ? 260 : 196;   // pad % 32 == 4
    constexpr int NB4 = (32 * BN) / 4 / 384;       // 5 or 4 (exact)
    constexpr int ASZ = 128 * 36;                  // words per A buffer
    constexpr int BSZ = 32 * BNP;                  // words per B buffer

    extern __shared__ unsigned dyn_smem[];
    unsigned* As = dyn_smem;                       // 2 buffers
    unsigned* Bs = dyn_smem + 2 * ASZ;             // 2 buffers

    const float* Ap = (EPI == 0) ? A : (const float*)g_ao;

    int tid  = threadIdx.x;
    int wid  = tid >> 5;
    int lane = tid & 31;
    int g    = lane >> 2;
    int t    = lane & 3;
    int wm   = wid / 3;
    int wn   = wid % 3;
    int m0   = blockIdx.x * 128;

    float4 pa[3];
    float4 pb[NB4];

    auto load_tile = [&](int ko) {
        #pragma unroll
        for (int j = 0; j < 3; j++) {
            int i = tid + j * 384;
            if (i < 1024) {
                int r = i >> 3, c = (i & 7) << 2;
                pa[j] = *(const float4*)(Ap + (size_t)(m0 + r) * CDIM + ko * 32 + c);
            }
        }
        #pragma unroll
        for (int j = 0; j < NB4; j++) {
            int e  = (tid + j * 384) * 4;
            int kr = e / BN, c = e % BN;           // c % 4 == 0; no segment straddle
            if (EPI == 0) {
                pb[j] = (c < 192)
                    ? *(const float4*)(B0 + (ko * 32 + kr) * 192 + c)
                    : *(const float4*)(B1 + (ko * 32 + kr) * 48 + (c - 192));
            } else {
                pb[j] = *(const float4*)(B0 + (ko * 32 + kr) * 192 + c);
            }
        }
    };

    auto store_tile = [&](int buf) {
        unsigned* Aw = As + buf * ASZ;
        unsigned* Bw = Bs + buf * BSZ;
        #pragma unroll
        for (int j = 0; j < 3; j++) {
            int i = tid + j * 384;
            if (i < 1024) {
                int r = i >> 3, c = (i & 7) << 2;
                Aw[r * 36 + c + 0] = f2tf(pa[j].x);
                Aw[r * 36 + c + 1] = f2tf(pa[j].y);
                Aw[r * 36 + c + 2] = f2tf(pa[j].z);
                Aw[r * 36 + c + 3] = f2tf(pa[j].w);
            }
        }
        #pragma unroll
        for (int j = 0; j < NB4; j++) {
            int e  = (tid + j * 384) * 4;
            int kr = e / BN, c = e % BN;
            Bw[kr * BNP + c + 0] = f2tf(pb[j].x);
            Bw[kr * BNP + c + 1] = f2tf(pb[j].y);
            Bw[kr * BNP + c + 2] = f2tf(pb[j].z);
            Bw[kr * BNP + c + 3] = f2tf(pb[j].w);
        }
    };

    float acc[2][NTW][4];
    #pragma unroll
    for (int mt = 0; mt < 2; mt++)
        #pragma unroll
        for (int nt = 0; nt < NTW; nt++)
            #pragma unroll
            for (int j = 0; j < 4; j++) acc[mt][nt][j] = 0.f;

    // prologue
    load_tile(0);
    store_tile(0);
    __syncthreads();

    for (int ko = 0; ko < 6; ko++) {               // K = 192 = 6*32
        if (ko < 5) load_tile(ko + 1);             // LDG in flight during compute

        const unsigned* Ar = As + (ko & 1) * ASZ;
        const unsigned* Br = Bs + (ko & 1) * BSZ;
        #pragma unroll
        for (int kk = 0; kk < 4; kk++) {
            unsigned a[2][4];
            #pragma unroll
            for (int mt = 0; mt < 2; mt++) {
                int row = wm * 32 + mt * 16;
                a[mt][0] = Ar[(row + g    ) * 36 + kk * 8 + t    ];
                a[mt][1] = Ar[(row + g + 8) * 36 + kk * 8 + t    ];
                a[mt][2] = Ar[(row + g    ) * 36 + kk * 8 + t + 4];
                a[mt][3] = Ar[(row + g + 8) * 36 + kk * 8 + t + 4];
            }
            unsigned b[NTW][2];
            #pragma unroll
            for (int nt = 0; nt < NTW; nt++) {
                int col = wn * WN + nt * 8 + g;
                b[nt][0] = Br[(kk * 8 + t    ) * BNP + col];
                b[nt][1] = Br[(kk * 8 + t + 4) * BNP + col];
            }
            #pragma unroll
            for (int mt = 0; mt < 2; mt++)
                #pragma unroll
                for (int nt = 0; nt < NTW; nt++)
                    mma8(acc[mt][nt], a[mt][0], a[mt][1], a[mt][2], a[mt][3], b[nt][0], b[nt][1]);
        }

        if (ko < 5) {
            store_tile((ko + 1) & 1);              // writes the OTHER buffer
            __syncthreads();                       // also fences reads of current buffer
        }
    }

    // epilogue
    #pragma unroll
    for (int mt = 0; mt < 2; mt++) {
        int r0 = m0 + wm * 32 + mt * 16 + g;
        int r1 = r0 + 8;
        #pragma unroll
        for (int nt = 0; nt < NTW; nt++) {
            int c0 = wn * WN + nt * 8 + 2 * t;
            int c1 = c0 + 1;
            if (EPI == 0) {
                epi0_store(r0, c0, acc[mt][nt][0], bias0, bias1);
                epi0_store(r0, c1, acc[mt][nt][1], bias0, bias1);
                epi0_store(r1, c0, acc[mt][nt][2], bias0, bias1);
                epi0_store(r1, c1, acc[mt][nt][3], bias0, bias1);
            } else {
                out[r0 * CDIM + c0] = acc[mt][nt][0] + bias0[c0];
                out[r0 * CDIM + c1] = acc[mt][nt][1] + bias0[c1];
                out[r1 * CDIM + c0] = acc[mt][nt][2] + bias0[c0];
                out[r1 * CDIM + c1] = acc[mt][nt][3] + bias0[c1];
            }
        }
    }
}

// ---------------------------------------------------------------------------
// K2: attention. grid (512, 6), 256 threads (8 warps). (unchanged this round)
// ---------------------------------------------------------------------------
__global__ __launch_bounds__(256)
void attn_kernel() {
    __shared__ unsigned ks[64][36];
    __shared__ unsigned vs[64][33];
    __shared__ float    bs[64][65];

    int b = blockIdx.x;
    int h = blockIdx.y;
    int tid = threadIdx.x;

    const float* kp = g_k + (size_t)(b * NH + h) * (PKV * HD);
    const float* vp = g_v + (size_t)(b * NH + h) * (PKV * HD);
    for (int i = tid; i < PKV * HD; i += 256) {
        ks[i >> 5][i & 31] = f2tf(kp[i]);
        vs[i >> 5][i & 31] = f2tf(vp[i]);
    }
    const float* bp = g_bias + h * 4096;
    for (int i = tid; i < 4096; i += 256) bs[i >> 6][i & 63] = bp[i];
    __syncthreads();

    int wid  = tid >> 5;
    int lane = tid & 31;
    int g    = lane >> 2;
    int t    = lane & 3;
    int qsrc = (lane & ~3) + (t >> 1);

    const float* qb = g_q  + (size_t)b * NTOK * CDIM + h * HD;
    float*       ob = g_ao + (size_t)b * NTOK * CDIM + h * HD;

    for (int it = 0; it < 4; it++) {
        int rowbase = it * 128 + wid * 16;

        float s[8][4];
        #pragma unroll
        for (int nt = 0; nt < 8; nt++)
            #pragma unroll
            for (int j = 0; j < 4; j++) s[nt][j] = 0.f;

        #pragma unroll
        for (int kk = 0; kk < 4; kk++) {
            unsigned a0 = f2tf(qb[(rowbase + g    ) * CDIM + kk * 8 + t    ]);
            unsigned a1 = f2tf(qb[(rowbase + g + 8) * CDIM + kk * 8 + t    ]);
            unsigned a2 = f2tf(qb[(rowbase + g    ) * CDIM + kk * 8 + t + 4]);
            unsigned a3 = f2tf(qb[(rowbase + g + 8) * CDIM + kk * 8 + t + 4]);
            #pragma unroll
            for (int nt = 0; nt < 8; nt++) {
                unsigned b0 = ks[nt * 8 + g][kk * 8 + t    ];
                unsigned b1 = ks[nt * 8 + g][kk * 8 + t + 4];
                mma8(s[nt], a0, a1, a2, a3, b0, b1);
            }
        }

        int r0 = rowbase + g, r1 = r0 + 8;
        int pq0 = pq_of(r0), pq1 = pq_of(r1);
        float m0 = -1e30f, m1 = -1e30f;
        #pragma unroll
        for (int nt = 0; nt < 8; nt++) {
            int c0 = nt * 8 + 2 * t;
            s[nt][0] += bs[pq0][c0];
            s[nt][1] += bs[pq0][c0 + 1];
            s[nt][2] += bs[pq1][c0];
            s[nt][3] += bs[pq1][c0 + 1];
            m0 = fmaxf(m0, fmaxf(s[nt][0], s[nt][1]));
            m1 = fmaxf(m1, fmaxf(s[nt][2], s[nt][3]));
        }
        m0 = fmaxf(m0, __shfl_xor_sync(0xffffffffu, m0, 1));
        m0 = fmaxf(m0, __shfl_xor_sync(0xffffffffu, m0, 2));
        m1 = fmaxf(m1, __shfl_xor_sync(0xffffffffu, m1, 1));
        m1 = fmaxf(m1, __shfl_xor_sync(0xffffffffu, m1, 2));
        float sum0 = 0.f, sum1 = 0.f;
        #pragma unroll
        for (int nt = 0; nt < 8; nt++) {
            s[nt][0] = __expf(s[nt][0] - m0); sum0 += s[nt][0];
            s[nt][1] = __expf(s[nt][1] - m0); sum0 += s[nt][1];
            s[nt][2] = __expf(s[nt][2] - m1); sum1 += s[nt][2];
            s[nt][3] = __expf(s[nt][3] - m1); sum1 += s[nt][3];
        }
        sum0 += __shfl_xor_sync(0xffffffffu, sum0, 1);
        sum0 += __shfl_xor_sync(0xffffffffu, sum0, 2);
        sum1 += __shfl_xor_sync(0xffffffffu, sum1, 1);
        sum1 += __shfl_xor_sync(0xffffffffu, sum1, 2);
        float inv0 = 1.f / sum0, inv1 = 1.f / sum1;

        unsigned pf[8][4];
        #pragma unroll
        for (int nt = 0; nt < 8; nt++) {
            pf[nt][0] = f2tf(s[nt][0] * inv0);
            pf[nt][1] = f2tf(s[nt][1] * inv0);
            pf[nt][2] = f2tf(s[nt][2] * inv1);
            pf[nt][3] = f2tf(s[nt][3] * inv1);
        }

        float o[4][4];
        #pragma unroll
        for (int on = 0; on < 4; on++)
            #pragma unroll
            for (int j = 0; j < 4; j++) o[on][j] = 0.f;

        #pragma unroll
        for (int kt = 0; kt < 8; kt++) {
            unsigned u00 = __shfl_sync(0xffffffffu, pf[kt][0], qsrc);
            unsigned u01 = __shfl_sync(0xffffffffu, pf[kt][1], qsrc);
            unsigned u10 = __shfl_sync(0xffffffffu, pf[kt][2], qsrc);
            unsigned u11 = __shfl_sync(0xffffffffu, pf[kt][3], qsrc);
            unsigned w00 = __shfl_sync(0xffffffffu, pf[kt][0], qsrc + 2);
            unsigned w01 = __shfl_sync(0xffffffffu, pf[kt][1], qsrc + 2);
            unsigned w10 = __shfl_sync(0xffffffffu, pf[kt][2], qsrc + 2);
            unsigned w11 = __shfl_sync(0xffffffffu, pf[kt][3], qsrc + 2);
            unsigned a0 = (t & 1) ? u01 : u00;
            unsigned a1 = (t & 1) ? u11 : u10;
            unsigned a2 = (t & 1) ? w01 : w00;
            unsigned a3 = (t & 1) ? w11 : w10;
            #pragma unroll
            for (int on = 0; on < 4; on++) {
                unsigned b0 = vs[kt * 8 + t    ][on * 8 + g];
                unsigned b1 = vs[kt * 8 + t + 4][on * 8 + g];
                mma8(o[on], a0, a1, a2, a3, b0, b1);
            }
        }

        #pragma unroll
        for (int on = 0; on < 4; on++) {
            int c0 = on * 8 + 2 * t;
            ob[r0 * CDIM + c0    ] = o[on][0];
            ob[r0 * CDIM + c0 + 1] = o[on][1];
            ob[r1 * CDIM + c0    ] = o[on][2];
            ob[r1 * CDIM + c0 + 1] = o[on][3];
        }
    }
}

// ---------------------------------------------------------------------------
// launch
// ---------------------------------------------------------------------------
extern "C" void kernel_launch(void* const* d_in, const int* in_sizes, int n_in,
                              void* d_out, int out_size) {
    const float* x          = (const float*)d_in[0];
    const float* wq         = (const float*)d_in[1];
    const float* bq         = (const float*)d_in[2];
    const float* wkv        = (const float*)d_in[3];
    const float* bkv        = (const float*)d_in[4];
    const float* bias_table = (const float*)d_in[5];
    const float* wproj      = (const float*)d_in[6];
    const float* bproj      = (const float*)d_in[7];
    const int*   rpi        = (const int*)d_in[8];
    float* out = (float*)d_out;

    // dynamic smem sizes (double-buffered): A 2*128*36 + B 2*32*BNP words
    const int smem_qkv  = (2 * 128 * 36 + 2 * 32 * 260) * 4;   // 103424 B
    const int smem_proj = (2 * 128 * 36 + 2 * 32 * 196) * 4;   //  87040 B
    cudaFuncSetAttribute((const void*)gemm_kernel<240, 0>,
                         cudaFuncAttributeMaxDynamicSharedMemorySize, smem_qkv);
    cudaFuncSetAttribute((const void*)gemm_kernel<192, 1>,
                         cudaFuncAttributeMaxDynamicSharedMemorySize, smem_proj);

    bias_kernel<<<(NH * 64 * 64 + 255) / 256, 256>>>(bias_table, rpi);
    gemm_kernel<240, 0><<<MROWS / 128, 384, smem_qkv>>>(x, wq, wkv, bq, bkv, nullptr);
    attn_kernel<<<dim3(BWIN, NH), 256>>>();
    gemm_kernel<192, 1><<<MROWS / 128, 384, smem_proj>>>(nullptr, wproj, nullptr, bproj, nullptr, out);
}

// round 9
// speedup vs baseline: 1.7982x; 1.1185x over previous
#include <cuda_runtime.h>
#include <cuda_bf16.h>
#include <cuda_fp16.h>

// ---------------------------------------------------------------------------
// PSA3D: permuted 3D window attention
//   B=512 windows, N=512 tokens/window, C=192, 6 heads x 32, P=64 kv tokens
// Pipeline:
//   K0: bias precompute
//   K1: fused qkv GEMM  (fp16 m16n8k16, double-buffered) -> g_q, g_k, g_v
//   K2: attention       per (b,h): tf32 mma, fragment softmax
//   K3: out proj GEMM   (fp16 m16n8k16, double-buffered) -> d_out
// ---------------------------------------------------------------------------

#define BWIN   512
#define NTOK   512
#define CDIM   192
#define NH     6
#define HD     32
#define PKV    64
#define MROWS  (BWIN * NTOK)          // 262144
#define SCALE_F 0.17677669529663687f  // 32^-0.5

__device__ __align__(16) float g_q [MROWS * CDIM];
__device__ __align__(16) float g_k [BWIN * NH * PKV * HD];
__device__ __align__(16) float g_v [BWIN * NH * PKV * HD];
__device__ __align__(16) float g_ao[MROWS * CDIM];
__device__ __align__(16) float g_bias[NH * 64 * 64];

// ---------------------------------------------------------------------------
__device__ __forceinline__ unsigned f2tf(float f) {
    unsigned u;
    asm("cvt.rna.tf32.f32 %0, %1;" : "=r"(u) : "f"(f));
    return u;
}

__device__ __forceinline__ unsigned pack_h2(float x, float y) {
    __half2 h = __floats2half2_rn(x, y);
    return *(unsigned*)&h;
}

// tf32 m16n8k8 (attention)
__device__ __forceinline__ void mma8(float* c, unsigned a0, unsigned a1, unsigned a2, unsigned a3,
                                     unsigned b0, unsigned b1) {
    asm volatile(
        "mma.sync.aligned.m16n8k8.row.col.f32.tf32.tf32.f32 "
        "{%0,%1,%2,%3}, {%4,%5,%6,%7}, {%8,%9}, {%0,%1,%2,%3};\n"
        : "+f"(c[0]), "+f"(c[1]), "+f"(c[2]), "+f"(c[3])
        : "r"(a0), "r"(a1), "r"(a2), "r"(a3), "r"(b0), "r"(b1));
}

// fp16 m16n8k16 (GEMMs), f32 accumulate
__device__ __forceinline__ void mma16(float* c, unsigned a0, unsigned a1, unsigned a2, unsigned a3,
                                      unsigned b0, unsigned b1) {
    asm volatile(
        "mma.sync.aligned.m16n8k16.row.col.f32.f16.f16.f32 "
        "{%0,%1,%2,%3}, {%4,%5,%6,%7}, {%8,%9}, {%0,%1,%2,%3};\n"
        : "+f"(c[0]), "+f"(c[1]), "+f"(c[2]), "+f"(c[3])
        : "r"(a0), "r"(a1), "r"(a2), "r"(a3), "r"(b0), "r"(b1));
}

__device__ __forceinline__ int pq_of(int n) {
    return ((n >> 7) << 4) | (((n >> 4) & 3) << 2) | ((n >> 1) & 3);
}

// ---------------------------------------------------------------------------
// K0: bias precompute
// ---------------------------------------------------------------------------
__global__ void bias_kernel(const float* __restrict__ bias_table, const int* __restrict__ rpi) {
    int i = blockIdx.x * blockDim.x + threadIdx.x;   // 24576
    if (i >= NH * 64 * 64) return;
    int h  = i >> 12;
    int pq = (i >> 6) & 63;
    int p  = i & 63;
    int pd = pq >> 4, ph = (pq >> 2) & 3, pw = pq & 3;
    int n  = pd * 128 + ph * 16 + pw * 2;
    int t  = rpi[n * 64 + p];
    g_bias[i] = bias_table[t * NH + h];
}

// ---------------------------------------------------------------------------
// GEMM: BM=128, BK=32, 384 threads (12 warps: 4M x 3N), fp16 mma m16n8k16.
// Register-staged double buffering, packed-half2 smem:
//   As[r][w] = pack(A[r][2w], A[r][2w+1])   row stride 20 words (bank-clean)
//   Bs[kw][n] = pack(B[2kw][n], B[2kw+1][n]) row stride BNP (BNP % 32 == 4)
// ---------------------------------------------------------------------------
__device__ __forceinline__ void epi0_store(int r, int c, float val,
                                           const float* __restrict__ bq,
                                           const float* __restrict__ bkv) {
    if (c < 192) {
        g_q[r * CDIM + c] = (val + bq[c]) * SCALE_F;
    } else {
        int ch = c - 192;
        float v = val + bkv[ch];
        int b = r >> 9, n = r & 511;
        int d_ = n >> 6, h_ = (n >> 3) & 7, w_ = n & 7;
        int p  = ((d_ >> 1) << 4) | ((h_ >> 1) << 2) | (w_ >> 1);
        int s  = ((d_ & 1) << 2) | ((h_ & 1) << 1) | (w_ & 1);
        int off = s * 48 + ch;
        if (off < 192) {
            g_k[((b * NH + (off >> 5)) * PKV + p) * HD + (off & 31)] = v;
        } else {
            int o2 = off - 192;
            g_v[((b * NH + (o2 >> 5)) * PKV + p) * HD + (o2 & 31)] = v;
        }
    }
}

template<int BN, int EPI>
__global__ __launch_bounds__(384)
void gemm_kernel(const float* __restrict__ A,
                 const float* __restrict__ B0,
                 const float* __restrict__ B1,
                 const float* __restrict__ bias0,
                 const float* __restrict__ bias1,
                 float* __restrict__ out) {
    constexpr int NTW = BN / 24;                   // 10 or 8
    constexpr int WN  = BN / 3;                    // 80 or 64
    constexpr int BNP = (BN == 240) ? 260 : 196;   // pad % 32 == 4
    constexpr int NB4 = (32 * BN) / 4 / 384;       // 5 or 4 (exact)
    constexpr int AST = 20;                        // A row stride in words
    constexpr int ASZ = 128 * AST;                 // words per A buffer
    constexpr int BSZ = 16 * BNP;                  // words per B buffer (16 k-pair rows)

    extern __shared__ unsigned dyn_smem[];
    unsigned* As = dyn_smem;                       // 2 buffers
    unsigned* Bs = dyn_smem + 2 * ASZ;             // 2 buffers

    const float* Ap = (EPI == 0) ? A : (const float*)g_ao;

    int tid  = threadIdx.x;
    int wid  = tid >> 5;
    int lane = tid & 31;
    int g    = lane >> 2;
    int t    = lane & 3;
    int wm   = wid / 3;
    int wn   = wid % 3;
    int m0   = blockIdx.x * 128;

    float4 pa[3];
    float4 pb[NB4];

    auto load_tile = [&](int ko) {
        #pragma unroll
        for (int j = 0; j < 3; j++) {
            int i = tid + j * 384;
            if (i < 1024) {
                int r = i >> 3, c = (i & 7) << 2;
                pa[j] = *(const float4*)(Ap + (size_t)(m0 + r) * CDIM + ko * 32 + c);
            }
        }
        #pragma unroll
        for (int j = 0; j < NB4; j++) {
            int e  = (tid + j * 384) * 4;
            int kr = e / BN, c = e % BN;           // c % 4 == 0; no segment straddle
            if (EPI == 0) {
                pb[j] = (c < 192)
                    ? *(const float4*)(B0 + (ko * 32 + kr) * 192 + c)
                    : *(const float4*)(B1 + (ko * 32 + kr) * 48 + (c - 192));
            } else {
                pb[j] = *(const float4*)(B0 + (ko * 32 + kr) * 192 + c);
            }
        }
    };

    auto store_tile = [&](int buf) {
        unsigned* Aw = As + buf * ASZ;
        __half*   Bh = (__half*)(Bs + buf * BSZ);
        #pragma unroll
        for (int j = 0; j < 3; j++) {
            int i = tid + j * 384;
            if (i < 1024) {
                int r = i >> 3, c = (i & 7) << 2;   // c in {0,4,...,28}
                Aw[r * AST + (c >> 1)    ] = pack_h2(pa[j].x, pa[j].y);
                Aw[r * AST + (c >> 1) + 1] = pack_h2(pa[j].z, pa[j].w);
            }
        }
        #pragma unroll
        for (int j = 0; j < NB4; j++) {
            int e  = (tid + j * 384) * 4;
            int kr = e / BN, c = e % BN;
            int base = ((kr >> 1) * BNP + c) * 2 + (kr & 1);  // half index
            Bh[base    ] = __float2half_rn(pb[j].x);
            Bh[base + 2] = __float2half_rn(pb[j].y);
            Bh[base + 4] = __float2half_rn(pb[j].z);
            Bh[base + 6] = __float2half_rn(pb[j].w);
        }
    };

    float acc[2][NTW][4];
    #pragma unroll
    for (int mt = 0; mt < 2; mt++)
        #pragma unroll
        for (int nt = 0; nt < NTW; nt++)
            #pragma unroll
            for (int j = 0; j < 4; j++) acc[mt][nt][j] = 0.f;

    // prologue
    load_tile(0);
    store_tile(0);
    __syncthreads();

    for (int ko = 0; ko < 6; ko++) {               // K = 192 = 6*32
        if (ko < 5) load_tile(ko + 1);             // LDG in flight during compute

        const unsigned* Ar = As + (ko & 1) * ASZ;
        const unsigned* Br = Bs + (ko & 1) * BSZ;
        #pragma unroll
        for (int kk = 0; kk < 2; kk++) {           // 2 x k16 per BK=32
            unsigned a[2][4];
            #pragma unroll
            for (int mt = 0; mt < 2; mt++) {
                int row = wm * 32 + mt * 16;
                a[mt][0] = Ar[(row + g    ) * AST + kk * 8 + t    ];
                a[mt][1] = Ar[(row + g + 8) * AST + kk * 8 + t    ];
                a[mt][2] = Ar[(row + g    ) * AST + kk * 8 + t + 4];
                a[mt][3] = Ar[(row + g + 8) * AST + kk * 8 + t + 4];
            }
            unsigned b[NTW][2];
            #pragma unroll
            for (int nt = 0; nt < NTW; nt++) {
                int col = wn * WN + nt * 8 + g;
                b[nt][0] = Br[(kk * 8 + t    ) * BNP + col];
                b[nt][1] = Br[(kk * 8 + t + 4) * BNP + col];
            }
            #pragma unroll
            for (int mt = 0; mt < 2; mt++)
                #pragma unroll
                for (int nt = 0; nt < NTW; nt++)
                    mma16(acc[mt][nt], a[mt][0], a[mt][1], a[mt][2], a[mt][3], b[nt][0], b[nt][1]);
        }

        if (ko < 5) {
            store_tile((ko + 1) & 1);              // writes the OTHER buffer
            __syncthreads();                       // also fences reads of current buffer
        }
    }

    // epilogue
    #pragma unroll
    for (int mt = 0; mt < 2; mt++) {
        int r0 = m0 + wm * 32 + mt * 16 + g;
        int r1 = r0 + 8;
        #pragma unroll
        for (int nt = 0; nt < NTW; nt++) {
            int c0 = wn * WN + nt * 8 + 2 * t;
            int c1 = c0 + 1;
            if (EPI == 0) {
                epi0_store(r0, c0, acc[mt][nt][0], bias0, bias1);
                epi0_store(r0, c1, acc[mt][nt][1], bias0, bias1);
                epi0_store(r1, c0, acc[mt][nt][2], bias0, bias1);
                epi0_store(r1, c1, acc[mt][nt][3], bias0, bias1);
            } else {
                out[r0 * CDIM + c0] = acc[mt][nt][0] + bias0[c0];
                out[r0 * CDIM + c1] = acc[mt][nt][1] + bias0[c1];
                out[r1 * CDIM + c0] = acc[mt][nt][2] + bias0[c0];
                out[r1 * CDIM + c1] = acc[mt][nt][3] + bias0[c1];
            }
        }
    }
}

// ---------------------------------------------------------------------------
// K2: attention. grid (512, 6), 256 threads (8 warps). (unchanged this round)
// ---------------------------------------------------------------------------
__global__ __launch_bounds__(256)
void attn_kernel() {
    __shared__ unsigned ks[64][36];
    __shared__ unsigned vs[64][33];
    __shared__ float    bs[64][65];

    int b = blockIdx.x;
    int h = blockIdx.y;
    int tid = threadIdx.x;

    const float* kp = g_k + (size_t)(b * NH + h) * (PKV * HD);
    const float* vp = g_v + (size_t)(b * NH + h) * (PKV * HD);
    for (int i = tid; i < PKV * HD; i += 256) {
        ks[i >> 5][i & 31] = f2tf(kp[i]);
        vs[i >> 5][i & 31] = f2tf(vp[i]);
    }
    const float* bp = g_bias + h * 4096;
    for (int i = tid; i < 4096; i += 256) bs[i >> 6][i & 63] = bp[i];
    __syncthreads();

    int wid  = tid >> 5;
    int lane = tid & 31;
    int g    = lane >> 2;
    int t    = lane & 3;
    int qsrc = (lane & ~3) + (t >> 1);

    const float* qb = g_q  + (size_t)b * NTOK * CDIM + h * HD;
    float*       ob = g_ao + (size_t)b * NTOK * CDIM + h * HD;

    for (int it = 0; it < 4; it++) {
        int rowbase = it * 128 + wid * 16;

        float s[8][4];
        #pragma unroll
        for (int nt = 0; nt < 8; nt++)
            #pragma unroll
            for (int j = 0; j < 4; j++) s[nt][j] = 0.f;

        #pragma unroll
        for (int kk = 0; kk < 4; kk++) {
            unsigned a0 = f2tf(qb[(rowbase + g    ) * CDIM + kk * 8 + t    ]);
            unsigned a1 = f2tf(qb[(rowbase + g + 8) * CDIM + kk * 8 + t    ]);
            unsigned a2 = f2tf(qb[(rowbase + g    ) * CDIM + kk * 8 + t + 4]);
            unsigned a3 = f2tf(qb[(rowbase + g + 8) * CDIM + kk * 8 + t + 4]);
            #pragma unroll
            for (int nt = 0; nt < 8; nt++) {
                unsigned b0 = ks[nt * 8 + g][kk * 8 + t    ];
                unsigned b1 = ks[nt * 8 + g][kk * 8 + t + 4];
                mma8(s[nt], a0, a1, a2, a3, b0, b1);
            }
        }

        int r0 = rowbase + g, r1 = r0 + 8;
        int pq0 = pq_of(r0), pq1 = pq_of(r1);
        float m0 = -1e30f, m1 = -1e30f;
        #pragma unroll
        for (int nt = 0; nt < 8; nt++) {
            int c0 = nt * 8 + 2 * t;
            s[nt][0] += bs[pq0][c0];
            s[nt][1] += bs[pq0][c0 + 1];
            s[nt][2] += bs[pq1][c0];
            s[nt][3] += bs[pq1][c0 + 1];
            m0 = fmaxf(m0, fmaxf(s[nt][0], s[nt][1]));
            m1 = fmaxf(m1, fmaxf(s[nt][2], s[nt][3]));
        }
        m0 = fmaxf(m0, __shfl_xor_sync(0xffffffffu, m0, 1));
        m0 = fmaxf(m0, __shfl_xor_sync(0xffffffffu, m0, 2));
        m1 = fmaxf(m1, __shfl_xor_sync(0xffffffffu, m1, 1));
        m1 = fmaxf(m1, __shfl_xor_sync(0xffffffffu, m1, 2));
        float sum0 = 0.f, sum1 = 0.f;
        #pragma unroll
        for (int nt = 0; nt < 8; nt++) {
            s[nt][0] = __expf(s[nt][0] - m0); sum0 += s[nt][0];
            s[nt][1] = __expf(s[nt][1] - m0); sum0 += s[nt][1];
            s[nt][2] = __expf(s[nt][2] - m1); sum1 += s[nt][2];
            s[nt][3] = __expf(s[nt][3] - m1); sum1 += s[nt][3];
        }
        sum0 += __shfl_xor_sync(0xffffffffu, sum0, 1);
        sum0 += __shfl_xor_sync(0xffffffffu, sum0, 2);
        sum1 += __shfl_xor_sync(0xffffffffu, sum1, 1);
        sum1 += __shfl_xor_sync(0xffffffffu, sum1, 2);
        float inv0 = 1.f / sum0, inv1 = 1.f / sum1;

        unsigned pf[8][4];
        #pragma unroll
        for (int nt = 0; nt < 8; nt++) {
            pf[nt][0] = f2tf(s[nt][0] * inv0);
            pf[nt][1] = f2tf(s[nt][1] * inv0);
            pf[nt][2] = f2tf(s[nt][2] * inv1);
            pf[nt][3] = f2tf(s[nt][3] * inv1);
        }

        float o[4][4];
        #pragma unroll
        for (int on = 0; on < 4; on++)
            #pragma unroll
            for (int j = 0; j < 4; j++) o[on][j] = 0.f;

        #pragma unroll
        for (int kt = 0; kt < 8; kt++) {
            unsigned u00 = __shfl_sync(0xffffffffu, pf[kt][0], qsrc);
            unsigned u01 = __shfl_sync(0xffffffffu, pf[kt][1], qsrc);
            unsigned u10 = __shfl_sync(0xffffffffu, pf[kt][2], qsrc);
            unsigned u11 = __shfl_sync(0xffffffffu, pf[kt][3], qsrc);
            unsigned w00 = __shfl_sync(0xffffffffu, pf[kt][0], qsrc + 2);
            unsigned w01 = __shfl_sync(0xffffffffu, pf[kt][1], qsrc + 2);
            unsigned w10 = __shfl_sync(0xffffffffu, pf[kt][2], qsrc + 2);
            unsigned w11 = __shfl_sync(0xffffffffu, pf[kt][3], qsrc + 2);
            unsigned a0 = (t & 1) ? u01 : u00;
            unsigned a1 = (t & 1) ? u11 : u10;
            unsigned a2 = (t & 1) ? w01 : w00;
            unsigned a3 = (t & 1) ? w11 : w10;
            #pragma unroll
            for (int on = 0; on < 4; on++) {
                unsigned b0 = vs[kt * 8 + t    ][on * 8 + g];
                unsigned b1 = vs[kt * 8 + t + 4][on * 8 + g];
                mma8(o[on], a0, a1, a2, a3, b0, b1);
            }
        }

        #pragma unroll
        for (int on = 0; on < 4; on++) {
            int c0 = on * 8 + 2 * t;
            ob[r0 * CDIM + c0    ] = o[on][0];
            ob[r0 * CDIM + c0 + 1] = o[on][1];
            ob[r1 * CDIM + c0    ] = o[on][2];
            ob[r1 * CDIM + c0 + 1] = o[on][3];
        }
    }
}

// ---------------------------------------------------------------------------
// launch
// ---------------------------------------------------------------------------
extern "C" void kernel_launch(void* const* d_in, const int* in_sizes, int n_in,
                              void* d_out, int out_size) {
    const float* x          = (const float*)d_in[0];
    const float* wq         = (const float*)d_in[1];
    const float* bq         = (const float*)d_in[2];
    const float* wkv        = (const float*)d_in[3];
    const float* bkv        = (const float*)d_in[4];
    const float* bias_table = (const float*)d_in[5];
    const float* wproj      = (const float*)d_in[6];
    const float* bproj      = (const float*)d_in[7];
    const int*   rpi        = (const int*)d_in[8];
    float* out = (float*)d_out;

    // dynamic smem (double-buffered, fp16 packed): A 2*128*20 + B 2*16*BNP words
    const int smem_qkv  = (2 * 128 * 20 + 2 * 16 * 260) * 4;   // 53760 B
    const int smem_proj = (2 * 128 * 20 + 2 * 16 * 196) * 4;   // 45568 B
    cudaFuncSetAttribute((const void*)gemm_kernel<240, 0>,
                         cudaFuncAttributeMaxDynamicSharedMemorySize, smem_qkv);
    cudaFuncSetAttribute((const void*)gemm_kernel<192, 1>,
                         cudaFuncAttributeMaxDynamicSharedMemorySize, smem_proj);

    bias_kernel<<<(NH * 64 * 64 + 255) / 256, 256>>>(bias_table, rpi);
    gemm_kernel<240, 0><<<MROWS / 128, 384, smem_qkv>>>(x, wq, wkv, bq, bkv, nullptr);
    attn_kernel<<<dim3(BWIN, NH), 256>>>();
    gemm_kernel<192, 1><<<MROWS / 128, 384, smem_proj>>>(nullptr, wproj, nullptr, bproj, nullptr, out);
}